// round 1
// baseline (speedup 1.0000x reference)
#include <cuda_runtime.h>
#include <math.h>

#define NN 100000
#define EE 400000
#define GG 4096
#define EMB 128
#define LN2F 0.6931471805599453f

__device__ float    g_ha  [NN * EMB];
__device__ float    g_hb  [NN * EMB];
__device__ float    g_PQ  [NN * 2 * EMB];
__device__ float    g_S   [NN * EMB];
__device__ float    g_Rm  [NN * EMB];
__device__ float    g_acc [NN * EMB];
__device__ unsigned g_agg [NN * EMB];
__device__ int      g_deg [NN];
__device__ float    g_pool[GG * EMB];
__device__ float    g_comb[EMB * 2 * EMB];
__device__ float    g_cvec[EMB];

__device__ __forceinline__ float sp(float x) {
    return fmaxf(x, 0.f) + log1pf(expf(-fabsf(x)));
}
__device__ __forceinline__ unsigned fkey(float f) {
    unsigned u = __float_as_uint(f);
    return (u & 0x80000000u) ? ~u : (u | 0x80000000u);
}
__device__ __forceinline__ float finv(unsigned u) {
    return (u & 0x80000000u) ? __uint_as_float(u & 0x7FFFFFFFu) : __uint_as_float(~u);
}

__global__ void embed_sp_kernel(const float* __restrict__ emb, const int* __restrict__ ids,
                                float* __restrict__ out, int rows) {
    int t = blockIdx.x * blockDim.x + threadIdx.x;
    if (t >= rows * 32) return;
    int n = t >> 5, l = t & 31;
    const float4* e4 = (const float4*)emb;
    float4 v = e4[ids[n] * 32 + l];
    float4 o = make_float4(sp(v.x), sp(v.y), sp(v.z), sp(v.w));
    ((float4*)out)[(size_t)n * 32 + l] = o;
}

__global__ void count_deg_kernel(const int* __restrict__ dst) {
    int e = blockIdx.x * blockDim.x + threadIdx.x;
    if (e < EE) atomicAdd(&g_deg[dst[e]], 1);
}

__global__ void build_comb_kernel(const float* __restrict__ Wb) {
    int idx = blockIdx.x * blockDim.x + threadIdx.x;
    if (idx >= EMB * 2 * EMB) return;
    int k = idx >> 8, j = idx & 255;
    float v;
    if (j < EMB) v = Wb[k * EMB + j] - Wb[(k + EMB) * EMB + j];
    else         v = Wb[(k + EMB) * EMB + (j - EMB)];
    g_comb[k * 256 + j] = v;
}

__global__ void build_cvec_kernel(const float* __restrict__ We) {
    int j = threadIdx.x;
    float s = 0.f;
    for (int k = 0; k < EMB; k++) s += We[k * EMB + j];
    g_cvec[j] = LN2F * s;
}

__global__ void gemm_k128(const float* __restrict__ A, const float* __restrict__ W,
                          float* __restrict__ C, int M, int Nc) {
    __shared__ __align__(16) float As[16][68];
    __shared__ __align__(16) float Ws[16][128];
    int bm = blockIdx.x * 64;
    int bn = blockIdx.y * 128;
    int tid = threadIdx.x;
    int tm0 = (tid >> 5) * 8;
    int tn0 = (tid & 31) * 4;
    float acc[8][4];
#pragma unroll
    for (int i = 0; i < 8; i++)
#pragma unroll
        for (int j = 0; j < 4; j++) acc[i][j] = 0.f;

    int la_col = tid & 15;
    int la_row = tid >> 4;
    int lw_col = tid & 127;
    int lw_row = tid >> 7;

    for (int kb = 0; kb < 128; kb += 16) {
#pragma unroll
        for (int i = 0; i < 4; i++) {
            int row = la_row + i * 16;
            int gr = bm + row;
            As[la_col][row] = (gr < M) ? A[(size_t)gr * 128 + kb + la_col] : 0.f;
        }
#pragma unroll
        for (int i = 0; i < 8; i++) {
            int kr = lw_row + i * 2;
            Ws[kr][lw_col] = W[(size_t)(kb + kr) * Nc + bn + lw_col];
        }
        __syncthreads();
#pragma unroll
        for (int k = 0; k < 16; k++) {
            float4 a0 = *(const float4*)&As[k][tm0];
            float4 a1 = *(const float4*)&As[k][tm0 + 4];
            float4 w  = *(const float4*)&Ws[k][tn0];
            float am[8] = {a0.x, a0.y, a0.z, a0.w, a1.x, a1.y, a1.z, a1.w};
            float wn[4] = {w.x, w.y, w.z, w.w};
#pragma unroll
            for (int i = 0; i < 8; i++)
#pragma unroll
                for (int j = 0; j < 4; j++) acc[i][j] += am[i] * wn[j];
        }
        __syncthreads();
    }
#pragma unroll
    for (int i = 0; i < 8; i++) {
        int gr = bm + tm0 + i;
        if (gr < M) {
            float4 o = make_float4(acc[i][0], acc[i][1], acc[i][2], acc[i][3]);
            *(float4*)&C[(size_t)gr * Nc + bn + tn0] = o;
        }
    }
}

__global__ void edge_max_kernel(const int* __restrict__ src, const int* __restrict__ dst) {
    int e = blockIdx.x * 8 + (threadIdx.x >> 5);
    if (e >= EE) return;
    int l = threadIdx.x & 31;
    int d = dst[e], s = src[e];
    const float4* PQ = (const float4*)g_PQ;
    float4 p = PQ[(size_t)d * 64 + l];
    float4 q = PQ[(size_t)s * 64 + 32 + l];
    unsigned* a = &g_agg[(size_t)d * 128 + l * 4];
    atomicMax(a + 0, fkey(p.x + q.x));
    atomicMax(a + 1, fkey(p.y + q.y));
    atomicMax(a + 2, fkey(p.z + q.z));
    atomicMax(a + 3, fkey(p.w + q.w));
}

__global__ void update_hb_kernel(const float* __restrict__ b_bond) {
    int idx = blockIdx.x * blockDim.x + threadIdx.x;
    if (idx >= NN * EMB) return;
    int n = idx >> 7, k = idx & 127;
    float v = (g_deg[n] > 0) ? sp(finv(g_agg[idx]) + b_bond[k]) : LN2F;
    g_hb[idx] = v;
}

__global__ void edge_add_kernel(const int* __restrict__ src, const int* __restrict__ dst) {
    int e = blockIdx.x * 8 + (threadIdx.x >> 5);
    if (e >= EE) return;
    int l = threadIdx.x & 31;
    int d = dst[e], s = src[e];
    float4 r = ((const float4*)g_Rm)[(size_t)s * 32 + l];
    float4 sv = (e < NN) ? ((const float4*)g_S)[(size_t)e * 32 + l]
                         : ((const float4*)g_cvec)[l];
    float* a = &g_acc[(size_t)d * 128 + l * 4];
    atomicAdd(a + 0, r.x + sv.x);
    atomicAdd(a + 1, r.y + sv.y);
    atomicAdd(a + 2, r.z + sv.z);
    atomicAdd(a + 3, r.w + sv.w);
}

__global__ void update_ha_kernel(const float* __restrict__ b_msg, const float* __restrict__ b_edge) {
    int idx = blockIdx.x * blockDim.x + threadIdx.x;
    if (idx >= NN * EMB) return;
    int n = idx >> 7, k = idx & 127;
    float b = b_msg[k] + b_edge[k];
    g_ha[idx] = sp(g_acc[idx] + (float)g_deg[n] * b + g_ha[idx]);
}

__global__ void pool_kernel(const int* __restrict__ batch) {
    int t = blockIdx.x * blockDim.x + threadIdx.x;
    if (t >= NN * 32) return;
    int n = t >> 5, l = t & 31;
    int g = batch[n];
    float4 v = ((const float4*)g_ha)[(size_t)n * 32 + l];
    float* p = &g_pool[(size_t)g * 128 + l * 4];
    atomicAdd(p + 0, v.x);
    atomicAdd(p + 1, v.y);
    atomicAdd(p + 2, v.z);
    atomicAdd(p + 3, v.w);
}

__global__ void readout_kernel(const float* __restrict__ Wr1, const float* __restrict__ br1,
                               const float* __restrict__ Wr2, const float* __restrict__ br2,
                               const float* __restrict__ Wr3, const float* __restrict__ br3,
                               float* __restrict__ out) {
    __shared__ float pv[128];
    __shared__ float h1[64];
    __shared__ float h2[64];
    __shared__ float red[2];
    int g = blockIdx.x;
    int t = threadIdx.x;
    pv[t]      = g_pool[(size_t)g * 128 + t];
    pv[t + 64] = g_pool[(size_t)g * 128 + 64 + t];
    __syncthreads();
    float a1 = br1[t];
#pragma unroll 8
    for (int k = 0; k < 128; k++) a1 += pv[k] * Wr1[k * 64 + t];
    h1[t] = sp(a1);
    __syncthreads();
    float a2 = br2[t];
#pragma unroll 8
    for (int k = 0; k < 64; k++) a2 += h1[k] * Wr2[k * 64 + t];
    h2[t] = sp(a2);
    __syncthreads();
    float v = h2[t] * Wr3[t];
#pragma unroll
    for (int o = 16; o > 0; o >>= 1) v += __shfl_down_sync(0xffffffffu, v, o);
    if ((t & 31) == 0) red[t >> 5] = v;
    __syncthreads();
    if (t == 0) out[g] = red[0] + red[1] + br3[0];
}

__global__ void write_ha_kernel(float* __restrict__ out) {
    int t = blockIdx.x * blockDim.x + threadIdx.x;
    if (t >= NN * 32) return;
    ((float4*)out)[t] = ((const float4*)g_ha)[t];
}
__global__ void write_hb_kernel(float* __restrict__ out) {
    int t = blockIdx.x * blockDim.x + threadIdx.x;
    if (t >= EE * 32) return;
    int e = t >> 5;
    float4 v;
    if (e < NN) v = ((const float4*)g_hb)[t];
    else        v = make_float4(LN2F, LN2F, LN2F, LN2F);
    ((float4*)out)[t] = v;
}

extern "C" void kernel_launch(void* const* d_in, const int* in_sizes, int n_in,
                              void* d_out, int out_size) {
    const int*   x_ids      = (const int*)d_in[0];
    const int*   edge_attr  = (const int*)d_in[1];
    const int*   edge_index = (const int*)d_in[2];
    const int*   batch      = (const int*)d_in[3];
    const float* emb_atom   = (const float*)d_in[4];
    const float* emb_bond   = (const float*)d_in[5];
    const float* W_bond     = (const float*)d_in[6];
    const float* b_bond     = (const float*)d_in[7];
    const float* W_msg      = (const float*)d_in[8];
    const float* b_msg      = (const float*)d_in[9];
    const float* W_edge     = (const float*)d_in[10];
    const float* b_edge     = (const float*)d_in[11];
    const float* W_r1       = (const float*)d_in[12];
    const float* b_r1       = (const float*)d_in[13];
    const float* W_r2       = (const float*)d_in[14];
    const float* b_r2       = (const float*)d_in[15];
    const float* W_r3       = (const float*)d_in[16];
    const float* b_r3       = (const float*)d_in[17];

    const int* src = edge_index;
    const int* dst = edge_index + EE;

    float* out_g  = (float*)d_out;
    float* out_ha = out_g + GG;
    float* out_hb = out_ha + (size_t)NN * EMB;

    void *p_agg, *p_acc, *p_deg, *p_pool, *p_ha, *p_hb, *p_PQ, *p_S, *p_Rm, *p_comb;
    cudaGetSymbolAddress(&p_agg,  g_agg);
    cudaGetSymbolAddress(&p_acc,  g_acc);
    cudaGetSymbolAddress(&p_deg,  g_deg);
    cudaGetSymbolAddress(&p_pool, g_pool);
    cudaGetSymbolAddress(&p_ha,   g_ha);
    cudaGetSymbolAddress(&p_hb,   g_hb);
    cudaGetSymbolAddress(&p_PQ,   g_PQ);
    cudaGetSymbolAddress(&p_S,    g_S);
    cudaGetSymbolAddress(&p_Rm,   g_Rm);
    cudaGetSymbolAddress(&p_comb, g_comb);

    const int T = 256;
    int blk_n32  = (NN * 32 + T - 1) / T;
    int blk_n128 = (NN * EMB + T - 1) / T;
    int blk_e    = EE / 8;
    int blk_e32  = (EE * 32 + T - 1) / T;
    int gm       = (NN + 63) / 64;

    cudaMemsetAsync(p_deg, 0, NN * sizeof(int));
    embed_sp_kernel<<<blk_n32, T>>>(emb_atom, x_ids, (float*)p_ha, NN);
    embed_sp_kernel<<<blk_n32, T>>>(emb_bond, edge_attr, (float*)p_hb, NN);
    count_deg_kernel<<<(EE + T - 1) / T, T>>>(dst);
    build_comb_kernel<<<(EMB * 2 * EMB + T - 1) / T, T>>>(W_bond);
    build_cvec_kernel<<<1, 128>>>(W_edge);

    for (int pass = 0; pass < 2; pass++) {
        dim3 gpq(gm, 2);
        gemm_k128<<<gpq, T>>>((const float*)p_hb, (const float*)p_comb, (float*)p_PQ, NN, 256);
        cudaMemsetAsync(p_agg, 0, (size_t)NN * EMB * sizeof(unsigned));
        edge_max_kernel<<<blk_e, T>>>(src, dst);
        update_hb_kernel<<<blk_n128, T>>>(b_bond);
        dim3 g1(gm, 1);
        gemm_k128<<<g1, T>>>((const float*)p_hb, W_edge, (float*)p_S, NN, 128);
        gemm_k128<<<g1, T>>>((const float*)p_ha, W_msg, (float*)p_Rm, NN, 128);
        cudaMemsetAsync(p_acc, 0, (size_t)NN * EMB * sizeof(float));
        edge_add_kernel<<<blk_e, T>>>(src, dst);
        update_ha_kernel<<<blk_n128, T>>>(b_msg, b_edge);
    }

    cudaMemsetAsync(p_pool, 0, (size_t)GG * EMB * sizeof(float));
    pool_kernel<<<blk_n32, T>>>(batch);
    readout_kernel<<<GG, 64>>>(W_r1, b_r1, W_r2, b_r2, W_r3, b_r3, out_g);

    write_ha_kernel<<<blk_n32, T>>>(out_ha);
    write_hb_kernel<<<blk_e32, T>>>(out_hb);
}